// round 9
// baseline (speedup 1.0000x reference)
#include <cuda_runtime.h>
#include <cuda_bf16.h>
#include <math.h>
#include <stdint.h>

// Problem dims
#define Bn 512
#define Tn 512
#define In 256
#define Hn 250

// ---------------- helpers ----------------------------------------------------
__device__ __forceinline__ uint32_t smem_u32(const void* p) {
    uint32_t a;
    asm("{ .reg .u64 t; cvta.to.shared.u64 t, %1; cvt.u32.u64 %0, t; }"
        : "=r"(a) : "l"(p));
    return a;
}
__device__ __forceinline__ uint32_t bf16x2_rn(float lo, float hi) {
    uint32_t r;
    asm("cvt.rn.bf16x2.f32 %0, %1, %2;" : "=r"(r) : "f"(hi), "f"(lo));
    return r;
}
__device__ __forceinline__ void ldsm4(uint32_t* r, uint32_t addr) {
    asm volatile("ldmatrix.sync.aligned.m8n8.x4.shared.b16 {%0,%1,%2,%3}, [%4];"
                 : "=r"(r[0]), "=r"(r[1]), "=r"(r[2]), "=r"(r[3]) : "r"(addr));
}
__device__ __forceinline__ void mma16816(float* c, const uint32_t* a,
                                         const uint32_t* b) {
    asm volatile(
        "mma.sync.aligned.m16n8k16.row.col.f32.bf16.bf16.f32 "
        "{%0,%1,%2,%3}, {%4,%5,%6,%7}, {%8,%9}, {%0,%1,%2,%3};"
        : "+f"(c[0]), "+f"(c[1]), "+f"(c[2]), "+f"(c[3])
        : "r"(a[0]), "r"(a[1]), "r"(a[2]), "r"(a[3]), "r"(b[0]), "r"(b[1]));
}
#define CPASYNC16(dst, src) \
    asm volatile("cp.async.cg.shared.global [%0], [%1], 16;" \
                 :: "r"(dst), "l"(src))
#define CP_COMMIT() asm volatile("cp.async.commit_group;" ::: "memory")
#define CP_WAIT1()  asm volatile("cp.async.wait_group 1;" ::: "memory")

// fast tanh: 1 - 2/(e^{2x}+1), MUFU-based (abs err ~1e-6)
__device__ __forceinline__ float tanh_fast(float x) {
    float e;
    asm("ex2.approx.f32 %0, %1;" : "=f"(e) : "f"(x * 2.8853900817779268f));
    float r;
    asm("rcp.approx.f32 %0, %1;" : "=f"(r) : "f"(e + 1.0f));
    return fmaf(-2.0f, r, 1.0f);
}

// ---------------- scratch ----------------------------------------------------
__device__ float g_WhP[Hn * 256];                       // Wh padded [250][256]
__device__ unsigned short g_WxH[256 * 256];             // Wx hi bf16 [n][k]
__device__ unsigned short g_WxL[256 * 256];             // Wx lo bf16 [n][k]
__device__ unsigned short g_XH[(size_t)Bn * Tn * In];   // x hi bf16 (128 MB)
__device__ unsigned short g_XL[(size_t)Bn * Tn * In];   // x lo bf16 (128 MB)

__global__ void prep_whp_kernel(const float* __restrict__ Wh) {
    int i = blockIdx.x * blockDim.x + threadIdx.x;
    int r = i >> 8;
    int k = i & 255;
    g_WhP[i] = (k < Hn) ? Wh[r * Hn + k] : 0.0f;
}

__global__ void prep_wx_kernel(const float* __restrict__ Wx) {
    int i = blockIdx.x * blockDim.x + threadIdx.x;   // 256*256
    int r = i >> 8;
    int k = i & 255;
    float w = (r < Hn) ? Wx[r * In + k] : 0.0f;
    uint32_t wb = __float_as_uint(w);
    float hif = __uint_as_float(wb & 0xFFFF0000u);
    g_WxH[i] = (unsigned short)(wb >> 16);
    g_WxL[i] = __bfloat16_as_ushort(__float2bfloat16(w - hif));
}

__global__ void prep_x_kernel(const float* __restrict__ X) {
    size_t i = (size_t)blockIdx.x * blockDim.x + threadIdx.x;   // float4 id
    float4 v = ((const float4*)X)[i];
    uint2 hp, lp;
    hp.x = __byte_perm(__float_as_uint(v.x), __float_as_uint(v.y), 0x7632);
    hp.y = __byte_perm(__float_as_uint(v.z), __float_as_uint(v.w), 0x7632);
    #define REM(f) ((f) - __uint_as_float(__float_as_uint(f) & 0xFFFF0000u))
    lp.x = bf16x2_rn(REM(v.x), REM(v.y));
    lp.y = bf16x2_rn(REM(v.z), REM(v.w));
    #undef REM
    ((uint2*)g_XH)[i] = hp;
    ((uint2*)g_XL)[i] = lp;
}

// ---------------- Phase 1: xproj via HMMA bf16-split GEMM (v3) ---------------
// CTA tile 128M x 256N x 32K-chunk, warp tile 32x128, cp.async double buffer.
// X read exactly once from DRAM.
#define SBH    80                   // smem row stride bytes (32 bf16 + pad)
#define RBUF_A (128 * SBH)          // 10240 B
#define RBUF_B (256 * SBH)          // 20480 B
#define STG    (2 * RBUF_A + 2 * RBUF_B)   // Ah, Al, Bh, Bl = 61440 B
#define SMTOT  (2 * STG)            // 122880 B

__global__ __launch_bounds__(256, 1)
void gemm_xproj_hmma(float* __restrict__ out) {
    extern __shared__ __align__(16) char smc[];
    const uint32_t smb = smem_u32(smc);

    const int tid  = threadIdx.x;
    const int lane = tid & 31;
    const int warp = tid >> 5;
    const int wm = warp >> 1;              // 0..3 -> M offset 32*wm
    const int wn = warp & 1;               // 0..1 -> N offset 128*wn
    const size_t m0 = (size_t)blockIdx.x * 128;

    const int r0 = tid >> 1, c40 = (tid & 1) * 2;   // rows 0..127, c4 {0,2}
    const char* gxh = (const char*)g_XH;
    const char* gxl = (const char*)g_XL;
    const char* gwh = (const char*)g_WxH;
    const char* gwl = (const char*)g_WxL;

    float acc[2][16][4];
    #pragma unroll
    for (int mi = 0; mi < 2; mi++)
        #pragma unroll
        for (int ni = 0; ni < 16; ni++)
            #pragma unroll
            for (int q = 0; q < 4; q++) acc[mi][ni][q] = 0.0f;

    const uint32_t aoff = (uint32_t)((wm * 32 + (lane & 15)) * SBH + (lane >> 4) * 16);
    const uint32_t boff = (uint32_t)((wn * 128 + (lane >> 4) * 8 + (lane & 7)) * SBH +
                                     ((lane >> 3) & 1) * 16);

    auto load_stage = [&](int s, int k0) {
        uint32_t sb = smb + s * STG;
        #pragma unroll
        for (int i = 0; i < 2; i++) {
            int c4 = c40 + i;
            size_t ao = ((m0 + r0) * In + k0 + c4 * 8) * 2;
            uint32_t da = sb + r0 * SBH + c4 * 16;
            CPASYNC16(da,          gxh + ao);
            CPASYNC16(da + RBUF_A, gxl + ao);
            #pragma unroll
            for (int half = 0; half < 2; half++) {
                int rb = r0 + half * 128;
                size_t bo = ((size_t)rb * In + k0 + c4 * 8) * 2;
                uint32_t db = sb + 2 * RBUF_A + rb * SBH + c4 * 16;
                CPASYNC16(db,          gwh + bo);
                CPASYNC16(db + RBUF_B, gwl + bo);
            }
        }
    };

    load_stage(0, 0);  CP_COMMIT();
    load_stage(1, 32); CP_COMMIT();

    for (int c = 0; c < 8; c++) {
        CP_WAIT1();
        __syncthreads();

        const uint32_t sb  = smb + (c & 1) * STG;
        const uint32_t a_h = sb + aoff;
        const uint32_t a_l = sb + RBUF_A + aoff;
        const uint32_t b_h = sb + 2 * RBUF_A + boff;
        const uint32_t b_l = sb + 2 * RBUF_A + RBUF_B + boff;

        #pragma unroll
        for (int ks = 0; ks < 2; ks++) {
            const uint32_t ko = ks * 32;
            uint32_t ahf[2][4], alf[2][4];
            ldsm4(ahf[0], a_h + ko);
            ldsm4(ahf[1], a_h + 16 * SBH + ko);
            ldsm4(alf[0], a_l + ko);
            ldsm4(alf[1], a_l + 16 * SBH + ko);
            #pragma unroll
            for (int jp = 0; jp < 8; jp++) {
                uint32_t r[4];
                ldsm4(r, b_h + jp * 16 * SBH + ko);
                #pragma unroll
                for (int mi = 0; mi < 2; mi++) {
                    mma16816(acc[mi][jp * 2],     ahf[mi], r);
                    mma16816(acc[mi][jp * 2 + 1], ahf[mi], r + 2);
                    mma16816(acc[mi][jp * 2],     alf[mi], r);
                    mma16816(acc[mi][jp * 2 + 1], alf[mi], r + 2);
                }
            }
            #pragma unroll
            for (int jp = 0; jp < 8; jp++) {
                uint32_t r[4];
                ldsm4(r, b_l + jp * 16 * SBH + ko);
                #pragma unroll
                for (int mi = 0; mi < 2; mi++) {
                    mma16816(acc[mi][jp * 2],     ahf[mi], r);
                    mma16816(acc[mi][jp * 2 + 1], ahf[mi], r + 2);
                }
            }
        }
        __syncthreads();

        if (c + 2 < 8) load_stage(c & 1, (c + 2) * 32);
        CP_COMMIT();
    }

    // ---- epilogue ----
    const int g = lane >> 2, tg = lane & 3;
    #pragma unroll
    for (int mi = 0; mi < 2; mi++) {
        size_t r = m0 + wm * 32 + mi * 16 + g;
        #pragma unroll
        for (int ni = 0; ni < 16; ni++) {
            int col = wn * 128 + ni * 8 + tg * 2;
            if (col < Hn) {
                *(float2*)(out + r * Hn + col) =
                    make_float2(acc[mi][ni][0], acc[mi][ni][1]);
                *(float2*)(out + (r + 8) * Hn + col) =
                    make_float2(acc[mi][ni][2], acc[mi][ni][3]);
            }
        }
    }
}

// ---------------- Phase 2: recurrent scan ------------------------------------
#define KC 220
#define KC4 (KC / 4)
#define WREG 9
#define HBUF 256
#define SCAN_SMEM_BYTES (Hn * KC * 4 + 2 * 4 * HBUF * 4)

__global__ __launch_bounds__(256, 1)
void rnn_scan_kernel(const float* __restrict__ h0,
                     const float* __restrict__ bh,
                     float* out) {
    extern __shared__ float sm[];
    float* WhS = sm;                    // [250][220]
    float* hb  = sm + Hn * KC;          // [2][4][256]

    const int j  = threadIdx.x;
    const int jj = (j < Hn) ? j : (Hn - 1);
    const int b0 = blockIdx.x * 4;

    for (int idx = j; idx < Hn * KC; idx += 256) {
        int r = idx / KC;
        int c = idx - r * KC;
        WhS[idx] = g_WhP[r * 256 + c];
    }
    for (int idx = j; idx < 2 * 4 * HBUF; idx += 256)
        hb[idx] = 0.0f;
    __syncthreads();
    if (j < Hn) {
        #pragma unroll
        for (int bb = 0; bb < 4; bb++)
            hb[bb * HBUF + j] = h0[(size_t)(b0 + bb) * Hn + j];
    }

    const float bias = bh[jj];

    float4 wg[WREG];
    {
        const float4* rowp = (const float4*)(g_WhP + (size_t)jj * 256);
        #pragma unroll
        for (int q = 0; q < WREG; q++)
            wg[q] = rowp[KC4 + q];
    }
    __syncthreads();

    int p = 0;
    for (int t = 0; t < Tn; t++) {
        float xp[4];
        if (j < Hn) {
            #pragma unroll
            for (int bb = 0; bb < 4; bb++)
                xp[bb] = out[((size_t)(b0 + bb) * Tn + t) * Hn + j];
        } else {
            xp[0] = xp[1] = xp[2] = xp[3] = 0.0f;
        }

        float acc[4];
        #pragma unroll
        for (int bb = 0; bb < 4; bb++) acc[bb] = bias;

        const float4* hbp = (const float4*)(hb + p * (4 * HBUF));
        const float4* wrow = (const float4*)(WhS + jj * KC);
        #pragma unroll 5
        for (int kc = 0; kc < KC4; kc++) {
            float4 w = wrow[kc];
            #pragma unroll
            for (int bb = 0; bb < 4; bb++) {
                float4 hv = hbp[bb * 64 + kc];
                acc[bb] += w.x * hv.x;
                acc[bb] += w.y * hv.y;
                acc[bb] += w.z * hv.z;
                acc[bb] += w.w * hv.w;
            }
        }
        #pragma unroll
        for (int q = 0; q < WREG; q++) {
            float4 w = wg[q];
            #pragma unroll
            for (int bb = 0; bb < 4; bb++) {
                float4 hv = hbp[bb * 64 + KC4 + q];
                acc[bb] += w.x * hv.x;
                acc[bb] += w.y * hv.y;
                acc[bb] += w.z * hv.z;
                acc[bb] += w.w * hv.w;
            }
        }

        float* hnx = hb + (1 - p) * (4 * HBUF);
        #pragma unroll
        for (int bb = 0; bb < 4; bb++) {
            float hv = tanh_fast(acc[bb] + xp[bb]);
            if (j < Hn) {
                hnx[bb * HBUF + j] = hv;
                out[((size_t)(b0 + bb) * Tn + t) * Hn + j] = hv;
            }
        }
        __syncthreads();
        p ^= 1;
    }
}

// ---------------- launch ------------------------------------------------------
extern "C" void kernel_launch(void* const* d_in, const int* in_sizes, int n_in,
                              void* d_out, int out_size) {
    const float* x  = (const float*)d_in[0];   // [512,512,256]
    const float* h0 = (const float*)d_in[1];   // [512,250]
    const float* Wx = (const float*)d_in[2];   // [250,256]
    const float* Wh = (const float*)d_in[3];   // [250,250]
    const float* bh = (const float*)d_in[4];   // [250]
    float* out = (float*)d_out;                // [512,512,250]

    // 1) weight + input prep
    prep_whp_kernel<<<Hn, 256>>>(Wh);
    prep_wx_kernel<<<256, 256>>>(Wx);
    prep_x_kernel<<<((size_t)Bn * Tn * In / 4) / 256, 256>>>(x);

    // 2) xproj HMMA GEMM (single X pass, double-buffered cp.async)
    cudaFuncSetAttribute(gemm_xproj_hmma,
                         cudaFuncAttributeMaxDynamicSharedMemorySize, SMTOT);
    gemm_xproj_hmma<<<(Bn * Tn) / 128, 256, SMTOT>>>(out);

    // 3) recurrent scan (in-place over d_out)
    cudaFuncSetAttribute(rnn_scan_kernel,
                         cudaFuncAttributeMaxDynamicSharedMemorySize,
                         SCAN_SMEM_BYTES);
    rnn_scan_kernel<<<(Bn / 4), 256, SCAN_SMEM_BYTES>>>(h0, bh, out);
}

// round 10
// speedup vs baseline: 1.3348x; 1.3348x over previous
#include <cuda_runtime.h>
#include <cuda_bf16.h>
#include <math.h>
#include <stdint.h>

// Problem dims
#define Bn 512
#define Tn 512
#define In 256
#define Hn 250

// ---------------- helpers ----------------------------------------------------
__device__ __forceinline__ uint32_t smem_u32(const void* p) {
    uint32_t a;
    asm("{ .reg .u64 t; cvta.to.shared.u64 t, %1; cvt.u32.u64 %0, t; }"
        : "=r"(a) : "l"(p));
    return a;
}
__device__ __forceinline__ uint32_t bf16x2_rn(float lo, float hi) {
    uint32_t r;
    asm("cvt.rn.bf16x2.f32 %0, %1, %2;" : "=r"(r) : "f"(hi), "f"(lo));
    return r;
}
__device__ __forceinline__ void ldsm4(uint32_t* r, uint32_t addr) {
    asm volatile("ldmatrix.sync.aligned.m8n8.x4.shared.b16 {%0,%1,%2,%3}, [%4];"
                 : "=r"(r[0]), "=r"(r[1]), "=r"(r[2]), "=r"(r[3]) : "r"(addr));
}
__device__ __forceinline__ void mma16816(float* c, const uint32_t* a,
                                         const uint32_t* b) {
    asm volatile(
        "mma.sync.aligned.m16n8k16.row.col.f32.bf16.bf16.f32 "
        "{%0,%1,%2,%3}, {%4,%5,%6,%7}, {%8,%9}, {%0,%1,%2,%3};"
        : "+f"(c[0]), "+f"(c[1]), "+f"(c[2]), "+f"(c[3])
        : "r"(a[0]), "r"(a[1]), "r"(a[2]), "r"(a[3]), "r"(b[0]), "r"(b[1]));
}
#define CPASYNC16(dst, src) \
    asm volatile("cp.async.cg.shared.global [%0], [%1], 16;" \
                 :: "r"(dst), "l"(src))
#define CP_COMMIT() asm volatile("cp.async.commit_group;" ::: "memory")
#define CP_WAIT1()  asm volatile("cp.async.wait_group 1;" ::: "memory")
#define CLUSTER_ARRIVE() asm volatile("barrier.cluster.arrive.aligned;" ::: "memory")
#define CLUSTER_WAIT()   asm volatile("barrier.cluster.wait.aligned;" ::: "memory")

__device__ __forceinline__ void sts_u32(uint32_t addr, uint32_t v) {
    asm volatile("st.shared.u32 [%0], %1;" :: "r"(addr), "r"(v));
}
__device__ __forceinline__ void sts_cluster_u32(uint32_t addr, uint32_t v) {
    asm volatile("st.shared::cluster.u32 [%0], %1;" :: "r"(addr), "r"(v));
}

// fast tanh: 1 - 2/(e^{2x}+1), MUFU-based (abs err ~1e-6)
__device__ __forceinline__ float tanh_fast(float x) {
    float e;
    asm("ex2.approx.f32 %0, %1;" : "=f"(e) : "f"(x * 2.8853900817779268f));
    float r;
    asm("rcp.approx.f32 %0, %1;" : "=f"(r) : "f"(e + 1.0f));
    return fmaf(-2.0f, r, 1.0f);
}

// ---------------- scratch ----------------------------------------------------
__device__ unsigned short g_WxH[256 * 256];             // Wx hi bf16 [n][k]
__device__ unsigned short g_WxL[256 * 256];             // Wx lo bf16 [n][k]
__device__ unsigned short g_WhH[256 * 256];             // Wh hi bf16 [n][k] padded
__device__ unsigned short g_WhL[256 * 256];             // Wh lo bf16 [n][k] padded
__device__ unsigned short g_XH[(size_t)Bn * Tn * In];   // x hi bf16 (128 MB)
__device__ unsigned short g_XL[(size_t)Bn * Tn * In];   // x lo bf16 (128 MB)

__global__ void prep_wx_kernel(const float* __restrict__ Wx) {
    int i = blockIdx.x * blockDim.x + threadIdx.x;   // 256*256
    int r = i >> 8;
    int k = i & 255;
    float w = (r < Hn) ? Wx[r * In + k] : 0.0f;
    uint32_t wb = __float_as_uint(w);
    float hif = __uint_as_float(wb & 0xFFFF0000u);
    g_WxH[i] = (unsigned short)(wb >> 16);
    g_WxL[i] = __bfloat16_as_ushort(__float2bfloat16(w - hif));
}

__global__ void prep_wh_kernel(const float* __restrict__ Wh) {
    int i = blockIdx.x * blockDim.x + threadIdx.x;   // 256*256
    int r = i >> 8;
    int k = i & 255;
    float w = (r < Hn && k < Hn) ? Wh[r * Hn + k] : 0.0f;
    uint32_t wb = __float_as_uint(w);
    float hif = __uint_as_float(wb & 0xFFFF0000u);
    g_WhH[i] = (unsigned short)(wb >> 16);
    g_WhL[i] = __bfloat16_as_ushort(__float2bfloat16(w - hif));
}

__global__ void prep_x_kernel(const float* __restrict__ X) {
    size_t i = (size_t)blockIdx.x * blockDim.x + threadIdx.x;   // float4 id
    float4 v = ((const float4*)X)[i];
    uint2 hp, lp;
    hp.x = __byte_perm(__float_as_uint(v.x), __float_as_uint(v.y), 0x7632);
    hp.y = __byte_perm(__float_as_uint(v.z), __float_as_uint(v.w), 0x7632);
    #define REM(f) ((f) - __uint_as_float(__float_as_uint(f) & 0xFFFF0000u))
    lp.x = bf16x2_rn(REM(v.x), REM(v.y));
    lp.y = bf16x2_rn(REM(v.z), REM(v.w));
    #undef REM
    ((uint2*)g_XH)[i] = hp;
    ((uint2*)g_XL)[i] = lp;
}

// ---------------- Phase 1: xproj via HMMA bf16-split GEMM (R8 proven) --------
#define SBH   80
#define RBUF  (128 * SBH)
#define STG   (4 * RBUF)
#define SMTOT (2 * STG)

__global__ __launch_bounds__(256, 2)
void gemm_xproj_hmma(float* __restrict__ out) {
    extern __shared__ __align__(16) char smc[];
    const uint32_t smb = smem_u32(smc);

    const int tid  = threadIdx.x;
    const int lane = tid & 31;
    const int warp = tid >> 5;
    const int wm = warp >> 1;
    const int wn = warp & 1;
    const size_t m0 = (size_t)blockIdx.x * 128;
    const int n0c = blockIdx.y * 128;

    const int r0 = tid >> 1, c40 = (tid & 1) * 2;
    const char* gxh = (const char*)g_XH;
    const char* gxl = (const char*)g_XL;
    const char* gwh = (const char*)g_WxH;
    const char* gwl = (const char*)g_WxL;

    float acc[2][8][4];
    #pragma unroll
    for (int mi = 0; mi < 2; mi++)
        #pragma unroll
        for (int ni = 0; ni < 8; ni++)
            #pragma unroll
            for (int q = 0; q < 4; q++) acc[mi][ni][q] = 0.0f;

    const uint32_t aoff = (uint32_t)((wm * 32 + (lane & 15)) * SBH + (lane >> 4) * 16);
    const uint32_t boff = (uint32_t)((wn * 64 + (lane >> 4) * 8 + (lane & 7)) * SBH +
                                     ((lane >> 3) & 1) * 16);

    auto load_stage = [&](int s, int k0) {
        uint32_t sb = smb + s * STG;
        #pragma unroll
        for (int i = 0; i < 2; i++) {
            int c4 = c40 + i;
            uint32_t d = sb + r0 * SBH + c4 * 16;
            size_t ao = ((m0 + r0) * In + k0 + c4 * 8) * 2;
            size_t bo = (((size_t)(n0c + r0)) * In + k0 + c4 * 8) * 2;
            CPASYNC16(d,            gxh + ao);
            CPASYNC16(d + RBUF,     gxl + ao);
            CPASYNC16(d + 2 * RBUF, gwh + bo);
            CPASYNC16(d + 3 * RBUF, gwl + bo);
        }
    };

    load_stage(0, 0);  CP_COMMIT();
    load_stage(1, 32); CP_COMMIT();

    for (int c = 0; c < 8; c++) {
        CP_WAIT1();
        __syncthreads();

        const uint32_t sb = smb + (c & 1) * STG;
        const uint32_t a_h = sb + aoff,            a_l = sb + RBUF + aoff;
        const uint32_t b_h = sb + 2 * RBUF + boff, b_l = sb + 3 * RBUF + boff;

        #pragma unroll
        for (int ks = 0; ks < 2; ks++) {
            const uint32_t ko = ks * 32;
            uint32_t ahf[2][4], alf[2][4], bf[8][2];
            ldsm4(ahf[0], a_h + ko);
            ldsm4(ahf[1], a_h + 16 * SBH + ko);
            ldsm4(alf[0], a_l + ko);
            ldsm4(alf[1], a_l + 16 * SBH + ko);
            #pragma unroll
            for (int jp = 0; jp < 4; jp++) {
                uint32_t r[4];
                ldsm4(r, b_h + jp * 16 * SBH + ko);
                bf[jp * 2][0] = r[0]; bf[jp * 2][1] = r[1];
                bf[jp * 2 + 1][0] = r[2]; bf[jp * 2 + 1][1] = r[3];
            }
            #pragma unroll
            for (int mi = 0; mi < 2; mi++)
                #pragma unroll
                for (int ni = 0; ni < 8; ni++) {
                    mma16816(acc[mi][ni], ahf[mi], bf[ni]);
                    mma16816(acc[mi][ni], alf[mi], bf[ni]);
                }
            #pragma unroll
            for (int jp = 0; jp < 4; jp++) {
                uint32_t r[4];
                ldsm4(r, b_l + jp * 16 * SBH + ko);
                bf[jp * 2][0] = r[0]; bf[jp * 2][1] = r[1];
                bf[jp * 2 + 1][0] = r[2]; bf[jp * 2 + 1][1] = r[3];
            }
            #pragma unroll
            for (int mi = 0; mi < 2; mi++)
                #pragma unroll
                for (int ni = 0; ni < 8; ni++)
                    mma16816(acc[mi][ni], ahf[mi], bf[ni]);
        }
        __syncthreads();

        if (c + 2 < 8) load_stage(c & 1, (c + 2) * 32);
        CP_COMMIT();
    }

    const int g = lane >> 2, tg = lane & 3;
    #pragma unroll
    for (int mi = 0; mi < 2; mi++) {
        size_t r = m0 + wm * 32 + mi * 16 + g;
        #pragma unroll
        for (int ni = 0; ni < 8; ni++) {
            int col = n0c + wn * 64 + ni * 8 + tg * 2;
            if (col < Hn) {
                *(float2*)(out + r * Hn + col) =
                    make_float2(acc[mi][ni][0], acc[mi][ni][1]);
                *(float2*)(out + (r + 8) * Hn + col) =
                    make_float2(acc[mi][ni][2], acc[mi][ni][3]);
            }
        }
    }
}

// ---------------- Phase 2: HMMA recurrent scan (2-CTA cluster) ---------------
// 64 CTAs = 32 clusters. Cluster handles 16 batches (M=16); CTA rank owns
// output cols [128r, 128r+128). Wh half (bf16 hi+lo) in smem; its mma fragments
// live in REGISTERS across all 512 steps. h (bf16 hi/lo, [16][264]) ping-pongs
// in smem; halves exchanged per step via st.shared::cluster + barrier.cluster.
#define S_WHH  16
#define S_WHL  (S_WHH + 128 * 528)          // 67584 each
#define S_HB   (S_WHL + 128 * 528)          // 135184
#define HB_SZ  16896                        // (hi + lo) [16][264] bf16
#define HB_LO  8448
#define S_TOT  (S_HB + 2 * HB_SZ)           // 168976 B

__global__ __launch_bounds__(256, 1) __cluster_dims__(2, 1, 1)
void rnn_scan_mma(const float* __restrict__ h0,
                  const float* __restrict__ bh,
                  float* out) {
    extern __shared__ __align__(16) char smc[];
    const uint32_t smb = smem_u32(smc);
    const int tid  = threadIdx.x;
    const int lane = tid & 31;
    const int warp = tid >> 5;
    uint32_t rank;
    asm("mov.u32 %0, %%cluster_ctarank;" : "=r"(rank));
    const int b0 = (blockIdx.x >> 1) * 16;       // batch base
    const int nh = rank * 128;                   // owned n-half base

    // ---- load Wh half (hi/lo) into smem, row stride 264 bf16 (=528 B)
    #pragma unroll
    for (int it = 0; it < 16; it++) {
        int u = tid + 256 * it;                  // 4096 uint4 total
        int n = u >> 5, kk = u & 31;
        uint32_t off = (uint32_t)(n * 528 + kk * 16);
        *(uint4*)(smc + S_WHH + off) = ((const uint4*)g_WhH)[(size_t)(nh + n) * 32 + kk];
        *(uint4*)(smc + S_WHL + off) = ((const uint4*)g_WhL)[(size_t)(nh + n) * 32 + kk];
    }
    // ---- init h buffer 0 with full h0 (both halves), bf16 hi/lo split
    for (int idx = tid; idx < 16 * 264; idx += 256) {
        int m = idx / 264, c = idx - m * 264;
        float v = (c < Hn) ? h0[(size_t)(b0 + m) * Hn + c] : 0.0f;
        uint32_t bv = __float_as_uint(v);
        *(unsigned short*)(smc + S_HB + m * 528 + c * 2) = (unsigned short)(bv >> 16);
        float r = v - __uint_as_float(bv & 0xFFFF0000u);
        *(unsigned short*)(smc + S_HB + HB_LO + m * 528 + c * 2) =
            __bfloat16_as_ushort(__float2bfloat16(r));
    }
    __syncthreads();

    // ---- Wh fragments -> registers (persistent across all steps)
    uint32_t bhf[16][4], blf[16][4];
    const uint32_t boff = (uint32_t)((16 * warp + ((lane >> 4) << 3) + (lane & 7)) * 528 +
                                     ((lane >> 3) & 1) * 16);
    #pragma unroll
    for (int ks = 0; ks < 16; ks++) {
        ldsm4(bhf[ks], smb + S_WHH + boff + ks * 32);
        ldsm4(blf[ks], smb + S_WHL + boff + ks * 32);
    }

    // ---- geometry + bias
    const int g = lane >> 2, tg = lane & 3;
    const int colA = nh + 16 * warp + 2 * tg;    // n-tile 0
    const int colB = colA + 8;                   // n-tile 1
    const float2 biasA = (colA < Hn) ? *(const float2*)(bh + colA) : make_float2(0.f, 0.f);
    const float2 biasB = (colB < Hn) ? *(const float2*)(bh + colB) : make_float2(0.f, 0.f);
    const uint32_t aoffs = (uint32_t)((lane & 15) * 528 + (lane >> 4) * 16);

    uint32_t peer_hb;
    asm("mapa.shared::cluster.u32 %0, %1, %2;"
        : "=r"(peer_hb) : "r"(smb + S_HB), "r"(rank ^ 1));

    for (int t = 0; t < Tn; t++) {
        if (t > 0) CLUSTER_WAIT();               // peer's step-(t-1) h delivered

        const uint32_t hbR = smb + S_HB + (uint32_t)(t & 1) * HB_SZ;

        // xp prefetch (consumed in epilogue ~1.5K cyc later)
        const size_t orow0 = ((size_t)(b0 + g) * Tn + t) * Hn;
        const size_t orow8 = ((size_t)(b0 + g + 8) * Tn + t) * Hn;
        float2 xpA0 = make_float2(0.f, 0.f), xpA8 = xpA0, xpB0 = xpA0, xpB8 = xpA0;
        if (colA < Hn) { xpA0 = *(const float2*)(out + orow0 + colA);
                         xpA8 = *(const float2*)(out + orow8 + colA); }
        if (colB < Hn) { xpB0 = *(const float2*)(out + orow0 + colB);
                         xpB8 = *(const float2*)(out + orow8 + colB); }

        float acc0[4] = {0.f, 0.f, 0.f, 0.f};
        float acc1[4] = {0.f, 0.f, 0.f, 0.f};

        #pragma unroll
        for (int ks = 0; ks < 16; ks++) {
            uint32_t ah[4], al[4];
            ldsm4(ah, hbR + aoffs + ks * 32);
            ldsm4(al, hbR + HB_LO + aoffs + ks * 32);
            mma16816(acc0, ah, bhf[ks]);
            mma16816(acc1, ah, bhf[ks] + 2);
            mma16816(acc0, ah, blf[ks]);
            mma16816(acc1, ah, blf[ks] + 2);
            mma16816(acc0, al, bhf[ks]);
            mma16816(acc1, al, bhf[ks] + 2);
        }

        // ---- epilogue: tanh, write out, split h -> own + peer next buffer
        const uint32_t hbW  = smb + S_HB + (uint32_t)((t + 1) & 1) * HB_SZ;
        const uint32_t phbW = peer_hb + (uint32_t)((t + 1) & 1) * HB_SZ;

        float vA0 = 0.f, vA1 = 0.f, vA2 = 0.f, vA3 = 0.f;
        if (colA < Hn) {
            vA0 = tanh_fast(acc0[0] + xpA0.x + biasA.x);
            vA1 = tanh_fast(acc0[1] + xpA0.y + biasA.y);
            vA2 = tanh_fast(acc0[2] + xpA8.x + biasA.x);
            vA3 = tanh_fast(acc0[3] + xpA8.y + biasA.y);
            *(float2*)(out + orow0 + colA) = make_float2(vA0, vA1);
            *(float2*)(out + orow8 + colA) = make_float2(vA2, vA3);
        }
        float vB0 = 0.f, vB1 = 0.f, vB2 = 0.f, vB3 = 0.f;
        if (colB < Hn) {
            vB0 = tanh_fast(acc1[0] + xpB0.x + biasB.x);
            vB1 = tanh_fast(acc1[1] + xpB0.y + biasB.y);
            vB2 = tanh_fast(acc1[2] + xpB8.x + biasB.x);
            vB3 = tanh_fast(acc1[3] + xpB8.y + biasB.y);
            *(float2*)(out + orow0 + colB) = make_float2(vB0, vB1);
            *(float2*)(out + orow8 + colB) = make_float2(vB2, vB3);
        }

        #define STORE_H(row, col, v0, v1) do {                                   \
            uint32_t hp = __byte_perm(__float_as_uint(v0), __float_as_uint(v1),  \
                                      0x7632);                                   \
            float r0_ = (v0) - __uint_as_float(__float_as_uint(v0) & 0xFFFF0000u);\
            float r1_ = (v1) - __uint_as_float(__float_as_uint(v1) & 0xFFFF0000u);\
            uint32_t lp = bf16x2_rn(r0_, r1_);                                   \
            uint32_t off_ = (uint32_t)((row) * 528 + (col) * 2);                 \
            sts_u32(hbW + off_, hp);                                             \
            sts_u32(hbW + HB_LO + off_, lp);                                     \
            sts_cluster_u32(phbW + off_, hp);                                    \
            sts_cluster_u32(phbW + HB_LO + off_, lp);                            \
        } while (0)

        STORE_H(g,     colA, vA0, vA1);
        STORE_H(g + 8, colA, vA2, vA3);
        STORE_H(g,     colB, vB0, vB1);
        STORE_H(g + 8, colB, vB2, vB3);
        #undef STORE_H

        __syncthreads();
        CLUSTER_ARRIVE();
    }
    CLUSTER_WAIT();   // balance final arrive; no CTA exits while peer may store
}

// ---------------- launch ------------------------------------------------------
extern "C" void kernel_launch(void* const* d_in, const int* in_sizes, int n_in,
                              void* d_out, int out_size) {
    const float* x  = (const float*)d_in[0];   // [512,512,256]
    const float* h0 = (const float*)d_in[1];   // [512,250]
    const float* Wx = (const float*)d_in[2];   // [250,256]
    const float* Wh = (const float*)d_in[3];   // [250,250]
    const float* bh = (const float*)d_in[4];   // [250]
    float* out = (float*)d_out;                // [512,512,250]

    // 1) weight + input prep
    prep_wx_kernel<<<256, 256>>>(Wx);
    prep_wh_kernel<<<256, 256>>>(Wh);
    prep_x_kernel<<<((size_t)Bn * Tn * In / 4) / 256, 256>>>(x);

    // 2) xproj HMMA GEMM (R8 shape: occ 2, grid.y = 2)
    cudaFuncSetAttribute(gemm_xproj_hmma,
                         cudaFuncAttributeMaxDynamicSharedMemorySize, SMTOT);
    dim3 grid((Bn * Tn) / 128, 2);
    gemm_xproj_hmma<<<grid, 256, SMTOT>>>(out);

    // 3) HMMA recurrent scan (clustered, in-place over d_out)
    cudaFuncSetAttribute(rnn_scan_mma,
                         cudaFuncAttributeMaxDynamicSharedMemorySize, S_TOT);
    rnn_scan_mma<<<Bn / 8, 256, S_TOT>>>(h0, bh, out);
}